// round 8
// baseline (speedup 1.0000x reference)
#include <cuda_runtime.h>
#include <cuda_bf16.h>
#include <stdint.h>
#include <math.h>

#define BATCH 4
#define SEQ   4096
#define DIM   512
#define MQKV  (BATCH * SEQ)   // 16384

// ---------------- scratch (__device__ globals; no allocs allowed) -----------
__device__ __nv_bfloat16 g_xh[(size_t)MQKV * DIM], g_xl[(size_t)MQKV * DIM];
__device__ __nv_bfloat16 g_Wh[3 * DIM * DIM],      g_Wl[3 * DIM * DIM];
__device__ __nv_bfloat16 g_Qh[(size_t)MQKV * DIM], g_Ql[(size_t)MQKV * DIM];
__device__ __nv_bfloat16 g_Kh[(size_t)MQKV * DIM], g_Kl[(size_t)MQKV * DIM];
__device__ float         g_V [(size_t)MQKV * DIM];
__device__ __nv_bfloat16 g_Vth[(size_t)MQKV * DIM], g_Vtl[(size_t)MQKV * DIM];
__device__ float         g_S [(size_t)BATCH * SEQ * SEQ];   // 268 MB
__device__ float         g_L [BATCH * SEQ];

// ---------------- helpers ----------------------------------------------------
static __device__ __forceinline__ uint32_t smem_u32(const void* p){
    uint32_t a;
    asm("{ .reg .u64 t; cvta.to.shared.u64 t, %1; cvt.u32.u64 %0, t; }" : "=r"(a) : "l"(p));
    return a;
}
static __device__ __forceinline__ void ldsm4(uint32_t* r, uint32_t addr){
    asm volatile("ldmatrix.sync.aligned.m8n8.x4.shared.b16 {%0,%1,%2,%3}, [%4];"
        : "=r"(r[0]), "=r"(r[1]), "=r"(r[2]), "=r"(r[3]) : "r"(addr));
}
static __device__ __forceinline__ void ldsm2(uint32_t* r, uint32_t addr){
    asm volatile("ldmatrix.sync.aligned.m8n8.x2.shared.b16 {%0,%1}, [%2];"
        : "=r"(r[0]), "=r"(r[1]) : "r"(addr));
}
static __device__ __forceinline__ void mma16816(float* c, const uint32_t* a, const uint32_t* b){
    asm volatile("mma.sync.aligned.m16n8k16.row.col.f32.bf16.bf16.f32 "
        "{%0,%1,%2,%3}, {%4,%5,%6,%7}, {%8,%9}, {%0,%1,%2,%3};"
        : "+f"(c[0]), "+f"(c[1]), "+f"(c[2]), "+f"(c[3])
        : "r"(a[0]), "r"(a[1]), "r"(a[2]), "r"(a[3]), "r"(b[0]), "r"(b[1]));
}

// ---------------- smem plan --------------------------------------------------
// 4 tiles per stage, each 128 rows x 32 bf16, row stride padded to 80 B
// (20*r mod 32 covers all banks -> conflict-free ldmatrix).
#define ROWB   80
#define TILE_B (128 * ROWB)          // 10240
#define T_AHI  0
#define T_ALO  (1 * TILE_B)
#define T_BHI  (2 * TILE_B)
#define T_BLO  (3 * TILE_B)
#define STAGE_B (4 * TILE_B)         // 40960
#define SM_TOTAL (2 * STAGE_B)       // 81920

// bf16 tile loader: 128 rows x 32 cols from row-major K-contiguous global.
static __device__ __forceinline__ void ldB(char* tile, const __nv_bfloat16* __restrict__ G,
                                           int rowbase, long long ld, int k0, int tid){
    const int row = tid >> 1, half = tid & 1;
    const uint4* src = (const uint4*)(G + (size_t)(rowbase + row) * ld + k0 + half * 16);
    char* d = tile + row * ROWB + half * 32;
    uint4 v0 = src[0], v1 = src[1];
    *(uint4*)(d)      = v0;
    *(uint4*)(d + 16) = v1;
}

// PV A loader: P = exp(S - L[k]) split to bf16 hi/lo.
static __device__ __forceinline__ void ldA_pv(char* thi, char* tlo,
        const float* __restrict__ Sb, const float* __restrict__ Lb,
        int qbase, int k0, int tid){
    const int row = tid >> 1, half = tid & 1;
    const float4* s = (const float4*)(Sb + (size_t)(qbase + row) * SEQ + k0 + half * 16);
    const float4* l = (const float4*)(Lb + k0 + half * 16);
    __align__(16) __nv_bfloat16 h[16];
    __align__(16) __nv_bfloat16 q[16];
    #pragma unroll
    for (int c = 0; c < 4; c++){
        float4 sv = s[c], lv = l[c];
        float p0 = __expf(sv.x - lv.x), p1 = __expf(sv.y - lv.y);
        float p2 = __expf(sv.z - lv.z), p3 = __expf(sv.w - lv.w);
        __nv_bfloat16 h0 = __float2bfloat16(p0), h1 = __float2bfloat16(p1);
        __nv_bfloat16 h2 = __float2bfloat16(p2), h3 = __float2bfloat16(p3);
        h[c*4+0] = h0; h[c*4+1] = h1; h[c*4+2] = h2; h[c*4+3] = h3;
        q[c*4+0] = __float2bfloat16(p0 - __bfloat162float(h0));
        q[c*4+1] = __float2bfloat16(p1 - __bfloat162float(h1));
        q[c*4+2] = __float2bfloat16(p2 - __bfloat162float(h2));
        q[c*4+3] = __float2bfloat16(p3 - __bfloat162float(h3));
    }
    char* dh = thi + row * ROWB + half * 32;
    char* dl = tlo + row * ROWB + half * 32;
    *(uint4*)(dh)      = ((const uint4*)h)[0];
    *(uint4*)(dh + 16) = ((const uint4*)h)[1];
    *(uint4*)(dl)      = ((const uint4*)q)[0];
    *(uint4*)(dl + 16) = ((const uint4*)q)[1];
}

// ---------------- bf16 3-split tensor GEMM NT --------------------------------
// C[M,Nc] = (Ah+Al)[M,K] @ (Bh+Bl)[Nc,K]^T (+bias). mode 0: fp32 out; mode 1:
// split out to Chi/Clo. 128x128 CTA tile, 8 warps of 64x32, K-chunk 32.
__global__ __launch_bounds__(256, 1) void gemm_bf16_nt(
    const __nv_bfloat16* __restrict__ Ahg, const __nv_bfloat16* __restrict__ Alg,
    const __nv_bfloat16* __restrict__ Bhg, const __nv_bfloat16* __restrict__ Blg,
    const float* __restrict__ bias,
    float* __restrict__ Cf, __nv_bfloat16* __restrict__ Chi, __nv_bfloat16* __restrict__ Clo,
    int K, int Nc, int mode, long long sA, long long sB, long long sC)
{
    extern __shared__ char smem[];
    const int tid = threadIdx.x, wid = tid >> 5, lane = tid & 31;
    const int browG = blockIdx.y * 128, bcolG = blockIdx.x * 128;
    const int z = blockIdx.z;

    const __nv_bfloat16* Ah = Ahg + (long long)z * sA;
    const __nv_bfloat16* Al = Alg + (long long)z * sA;
    const __nv_bfloat16* Bh = Bhg + (long long)z * sB;
    const __nv_bfloat16* Bl = Blg + (long long)z * sB;

    float acc[4][4][4];
    #pragma unroll
    for (int i = 0; i < 4; i++)
        #pragma unroll
        for (int j = 0; j < 4; j++)
            #pragma unroll
            for (int k = 0; k < 4; k++) acc[i][j][k] = 0.f;

    // prologue: chunk 0 -> stage 0
    ldB(smem + T_AHI, Ah, browG, K, 0, tid);
    ldB(smem + T_ALO, Al, browG, K, 0, tid);
    ldB(smem + T_BHI, Bh, bcolG, K, 0, tid);
    ldB(smem + T_BLO, Bl, bcolG, K, 0, tid);
    __syncthreads();

    const uint32_t sbase = smem_u32(smem);
    const int wm = (wid & 1) * 64;
    const int wn = (wid >> 1) * 32;
    const uint32_t aoffA = (uint32_t)((wm + (lane & 15)) * ROWB + (lane >> 4) * 16);
    const uint32_t aoffB = (uint32_t)((wn + (lane & 7)) * ROWB + ((lane >> 3) & 1) * 16);

    const int nch = K >> 5;
    for (int c = 0; c < nch; c++){
        const int p = c & 1;
        if (c + 1 < nch){
            char* st = smem + (p ^ 1) * STAGE_B;
            const int k0 = (c + 1) << 5;
            ldB(st + T_AHI, Ah, browG, K, k0, tid);
            ldB(st + T_ALO, Al, browG, K, k0, tid);
            ldB(st + T_BHI, Bh, bcolG, K, k0, tid);
            ldB(st + T_BLO, Bl, bcolG, K, k0, tid);
        }
        const uint32_t sb = sbase + p * STAGE_B;
        #pragma unroll
        for (int ks = 0; ks < 2; ks++){
            const uint32_t kb = ks * 32;
            uint32_t ah[4][4], al[4][4], bh[4][2], bl[4][2];
            #pragma unroll
            for (int mt = 0; mt < 4; mt++){
                ldsm4(ah[mt], sb + T_AHI + aoffA + mt * (16 * ROWB) + kb);
                ldsm4(al[mt], sb + T_ALO + aoffA + mt * (16 * ROWB) + kb);
            }
            #pragma unroll
            for (int nt = 0; nt < 4; nt++){
                ldsm2(bh[nt], sb + T_BHI + aoffB + nt * (8 * ROWB) + kb);
                ldsm2(bl[nt], sb + T_BLO + aoffB + nt * (8 * ROWB) + kb);
            }
            #pragma unroll
            for (int mt = 0; mt < 4; mt++)
                #pragma unroll
                for (int nt = 0; nt < 4; nt++){
                    mma16816(acc[mt][nt], ah[mt], bh[nt]);
                    mma16816(acc[mt][nt], ah[mt], bl[nt]);
                    mma16816(acc[mt][nt], al[mt], bh[nt]);
                }
        }
        __syncthreads();
    }

    // epilogue
    const int g = lane >> 2, t = lane & 3;
    #pragma unroll
    for (int mt = 0; mt < 4; mt++){
        #pragma unroll
        for (int nt = 0; nt < 4; nt++){
            const long long r  = browG + wm + mt * 16 + g;
            const int       cc = bcolG + wn + nt * 8 + t * 2;
            const float* a = acc[mt][nt];
            const float b0 = bias ? bias[cc]     : 0.f;
            const float b1 = bias ? bias[cc + 1] : 0.f;
            const float v0 = a[0] + b0, v1 = a[1] + b1;
            const float v2 = a[2] + b0, v3 = a[3] + b1;
            if (mode == 0){
                float* Cz = Cf + (long long)z * sC;
                *(float2*)(Cz + r * (long long)Nc + cc)       = make_float2(v0, v1);
                *(float2*)(Cz + (r + 8) * (long long)Nc + cc) = make_float2(v2, v3);
            } else {
                __nv_bfloat16 h0 = __float2bfloat16(v0), h1 = __float2bfloat16(v1);
                __nv_bfloat16 h2 = __float2bfloat16(v2), h3 = __float2bfloat16(v3);
                __nv_bfloat162 hh0; hh0.x = h0; hh0.y = h1;
                __nv_bfloat162 hh1; hh1.x = h2; hh1.y = h3;
                __nv_bfloat162 ll0;
                ll0.x = __float2bfloat16(v0 - __bfloat162float(h0));
                ll0.y = __float2bfloat16(v1 - __bfloat162float(h1));
                __nv_bfloat162 ll1;
                ll1.x = __float2bfloat16(v2 - __bfloat162float(h2));
                ll1.y = __float2bfloat16(v3 - __bfloat162float(h3));
                *(__nv_bfloat162*)(Chi + r * (long long)Nc + cc)       = hh0;
                *(__nv_bfloat162*)(Chi + (r + 8) * (long long)Nc + cc) = hh1;
                *(__nv_bfloat162*)(Clo + r * (long long)Nc + cc)       = ll0;
                *(__nv_bfloat162*)(Clo + (r + 8) * (long long)Nc + cc) = ll1;
            }
        }
    }
}

// ---------------- PV GEMM: O[q,d] = sum_k exp(S-L[k]) * Vt[d,k] --------------
__global__ __launch_bounds__(256, 1) void gemm_bf16_pv(
    const float* __restrict__ S, const float* __restrict__ L,
    const __nv_bfloat16* __restrict__ Vth, const __nv_bfloat16* __restrict__ Vtl,
    float* __restrict__ O)
{
    extern __shared__ char smem[];
    const int tid = threadIdx.x, wid = tid >> 5, lane = tid & 31;
    const int browG = blockIdx.y * 128, bcolG = blockIdx.x * 128;
    const int z = blockIdx.z;

    const float* Sb = S + (size_t)z * SEQ * SEQ;
    const float* Lb = L + (size_t)z * SEQ;
    const __nv_bfloat16* Bh = Vth + (size_t)z * DIM * SEQ;
    const __nv_bfloat16* Bl = Vtl + (size_t)z * DIM * SEQ;
    float* Ob = O + (size_t)z * SEQ * DIM;

    float acc[4][4][4];
    #pragma unroll
    for (int i = 0; i < 4; i++)
        #pragma unroll
        for (int j = 0; j < 4; j++)
            #pragma unroll
            for (int k = 0; k < 4; k++) acc[i][j][k] = 0.f;

    ldA_pv(smem + T_AHI, smem + T_ALO, Sb, Lb, browG, 0, tid);
    ldB(smem + T_BHI, Bh, bcolG, SEQ, 0, tid);
    ldB(smem + T_BLO, Bl, bcolG, SEQ, 0, tid);
    __syncthreads();

    const uint32_t sbase = smem_u32(smem);
    const int wm = (wid & 1) * 64;
    const int wn = (wid >> 1) * 32;
    const uint32_t aoffA = (uint32_t)((wm + (lane & 15)) * ROWB + (lane >> 4) * 16);
    const uint32_t aoffB = (uint32_t)((wn + (lane & 7)) * ROWB + ((lane >> 3) & 1) * 16);

    const int nch = SEQ >> 5;   // 128
    for (int c = 0; c < nch; c++){
        const int p = c & 1;
        if (c + 1 < nch){
            char* st = smem + (p ^ 1) * STAGE_B;
            const int k0 = (c + 1) << 5;
            ldA_pv(st + T_AHI, st + T_ALO, Sb, Lb, browG, k0, tid);
            ldB(st + T_BHI, Bh, bcolG, SEQ, k0, tid);
            ldB(st + T_BLO, Bl, bcolG, SEQ, k0, tid);
        }
        const uint32_t sb = sbase + p * STAGE_B;
        #pragma unroll
        for (int ks = 0; ks < 2; ks++){
            const uint32_t kb = ks * 32;
            uint32_t ah[4][4], al[4][4], bh[4][2], bl[4][2];
            #pragma unroll
            for (int mt = 0; mt < 4; mt++){
                ldsm4(ah[mt], sb + T_AHI + aoffA + mt * (16 * ROWB) + kb);
                ldsm4(al[mt], sb + T_ALO + aoffA + mt * (16 * ROWB) + kb);
            }
            #pragma unroll
            for (int nt = 0; nt < 4; nt++){
                ldsm2(bh[nt], sb + T_BHI + aoffB + nt * (8 * ROWB) + kb);
                ldsm2(bl[nt], sb + T_BLO + aoffB + nt * (8 * ROWB) + kb);
            }
            #pragma unroll
            for (int mt = 0; mt < 4; mt++)
                #pragma unroll
                for (int nt = 0; nt < 4; nt++){
                    mma16816(acc[mt][nt], ah[mt], bh[nt]);
                    mma16816(acc[mt][nt], ah[mt], bl[nt]);
                    mma16816(acc[mt][nt], al[mt], bh[nt]);
                }
        }
        __syncthreads();
    }

    const int g = lane >> 2, t = lane & 3;
    #pragma unroll
    for (int mt = 0; mt < 4; mt++)
        #pragma unroll
        for (int nt = 0; nt < 4; nt++){
            const long long r  = browG + wm + mt * 16 + g;
            const int       cc = bcolG + wn + nt * 8 + t * 2;
            const float* a = acc[mt][nt];
            *(float2*)(Ob + r * (long long)DIM + cc)       = make_float2(a[0], a[1]);
            *(float2*)(Ob + (r + 8) * (long long)DIM + cc) = make_float2(a[2], a[3]);
        }
}

// ---------------- small kernels ----------------------------------------------
__global__ void split_pair(const float* __restrict__ x, __nv_bfloat16* __restrict__ hi,
                           __nv_bfloat16* __restrict__ lo, long long n)
{
    long long i = (long long)blockIdx.x * blockDim.x + threadIdx.x;
    const long long stride = (long long)gridDim.x * blockDim.x;
    for (; i < n; i += stride){
        const float v = x[i];
        __nv_bfloat16 h = __float2bfloat16(v);
        hi[i] = h;
        lo[i] = __float2bfloat16(v - __bfloat162float(h));
    }
}

__global__ void transpose_split(const float* __restrict__ V,
                                __nv_bfloat16* __restrict__ Th, __nv_bfloat16* __restrict__ Tl)
{
    __shared__ float t[32][33];
    const int b = blockIdx.z;
    const int d0 = blockIdx.x * 32, k0 = blockIdx.y * 32;
    const float* Vb = V + (size_t)b * SEQ * DIM;
    #pragma unroll
    for (int r = 0; r < 4; r++)
        t[threadIdx.y + 8 * r][threadIdx.x] =
            Vb[(size_t)(k0 + threadIdx.y + 8 * r) * DIM + d0 + threadIdx.x];
    __syncthreads();
    __nv_bfloat16* Thb = Th + (size_t)b * DIM * SEQ;
    __nv_bfloat16* Tlb = Tl + (size_t)b * DIM * SEQ;
    #pragma unroll
    for (int r = 0; r < 4; r++){
        const float v = t[threadIdx.x][threadIdx.y + 8 * r];
        __nv_bfloat16 h = __float2bfloat16(v);
        const size_t idx = (size_t)(d0 + threadIdx.y + 8 * r) * SEQ + k0 + threadIdx.x;
        Thb[idx] = h;
        Tlb[idx] = __float2bfloat16(v - __bfloat162float(h));
    }
}

__global__ void col_lse(const float* __restrict__ S, float* __restrict__ L)
{
    const int b = blockIdx.y;
    const int k = blockIdx.x * 32 + threadIdx.x;
    const float* Sb = S + (size_t)b * SEQ * SEQ;

    float m = -INFINITY, s = 0.f;
    for (int q = threadIdx.y; q < SEQ; q += 8) {
        const float v = Sb[(size_t)q * SEQ + k];
        const float mn = fmaxf(m, v);
        s = s * __expf(m - mn) + __expf(v - mn);
        m = mn;
    }
    __shared__ float sm[8][33], ss[8][33];
    sm[threadIdx.y][threadIdx.x] = m;
    ss[threadIdx.y][threadIdx.x] = s;
    __syncthreads();
    if (threadIdx.y == 0) {
        float M = m, Sa = s;
        #pragma unroll
        for (int t = 1; t < 8; t++) {
            const float m2 = sm[t][threadIdx.x], s2 = ss[t][threadIdx.x];
            const float Mn = fmaxf(M, m2);
            Sa = Sa * __expf(M - Mn) + s2 * __expf(m2 - Mn);
            M = Mn;
        }
        L[b * SEQ + k] = M + __logf(Sa);
    }
}

// ---------------- launcher ---------------------------------------------------
extern "C" void kernel_launch(void* const* d_in, const int* in_sizes, int n_in,
                              void* d_out, int out_size)
{
    const float* x  = (const float*)d_in[0];
    const float* Wq = (const float*)d_in[1];
    const float* bq = (const float*)d_in[2];
    const float* Wk = (const float*)d_in[3];
    const float* bk = (const float*)d_in[4];
    const float* Wv = (const float*)d_in[5];
    const float* bv = (const float*)d_in[6];
    float* out = (float*)d_out;

    __nv_bfloat16 *xh, *xl, *Wh, *Wl, *Qh, *Ql, *Kh, *Kl, *Vth, *Vtl;
    float *Vf, *pS, *pL;
    cudaGetSymbolAddress((void**)&xh,  g_xh);  cudaGetSymbolAddress((void**)&xl,  g_xl);
    cudaGetSymbolAddress((void**)&Wh,  g_Wh);  cudaGetSymbolAddress((void**)&Wl,  g_Wl);
    cudaGetSymbolAddress((void**)&Qh,  g_Qh);  cudaGetSymbolAddress((void**)&Ql,  g_Ql);
    cudaGetSymbolAddress((void**)&Kh,  g_Kh);  cudaGetSymbolAddress((void**)&Kl,  g_Kl);
    cudaGetSymbolAddress((void**)&Vth, g_Vth); cudaGetSymbolAddress((void**)&Vtl, g_Vtl);
    cudaGetSymbolAddress((void**)&Vf,  g_V);
    cudaGetSymbolAddress((void**)&pS,  g_S);   cudaGetSymbolAddress((void**)&pL,  g_L);

    cudaFuncSetAttribute(gemm_bf16_nt, cudaFuncAttributeMaxDynamicSharedMemorySize, SM_TOTAL);
    cudaFuncSetAttribute(gemm_bf16_pv, cudaFuncAttributeMaxDynamicSharedMemorySize, SM_TOTAL);

    // 1) hi/lo splits
    split_pair<<<1024, 256>>>(x,  xh, xl, (long long)MQKV * DIM);
    split_pair<<<256, 256>>>(Wq, Wh + 0 * DIM * DIM, Wl + 0 * DIM * DIM, (long long)DIM * DIM);
    split_pair<<<256, 256>>>(Wk, Wh + 1 * DIM * DIM, Wl + 1 * DIM * DIM, (long long)DIM * DIM);
    split_pair<<<256, 256>>>(Wv, Wh + 2 * DIM * DIM, Wl + 2 * DIM * DIM, (long long)DIM * DIM);

    // 2) projections
    {
        dim3 g(DIM / 128, MQKV / 128, 1);
        gemm_bf16_nt<<<g, 256, SM_TOTAL>>>(xh, xl, Wh + 0 * DIM * DIM, Wl + 0 * DIM * DIM, bq,
                                           nullptr, Qh, Ql, DIM, DIM, 1, 0, 0, 0);
        gemm_bf16_nt<<<g, 256, SM_TOTAL>>>(xh, xl, Wh + 1 * DIM * DIM, Wl + 1 * DIM * DIM, bk,
                                           nullptr, Kh, Kl, DIM, DIM, 1, 0, 0, 0);
        gemm_bf16_nt<<<g, 256, SM_TOTAL>>>(xh, xl, Wh + 2 * DIM * DIM, Wl + 2 * DIM * DIM, bv,
                                           Vf, nullptr, nullptr, DIM, DIM, 0, 0, 0, 0);
    }

    // 3) V -> Vt with split
    transpose_split<<<dim3(DIM / 32, SEQ / 32, BATCH), dim3(32, 8)>>>(Vf, Vth, Vtl);

    // 4) S = Q @ K^T (batched)
    gemm_bf16_nt<<<dim3(SEQ / 128, SEQ / 128, BATCH), 256, SM_TOTAL>>>(
        Qh, Ql, Kh, Kl, nullptr, pS, nullptr, nullptr,
        DIM, SEQ, 0, (long long)SEQ * DIM, (long long)SEQ * DIM, (long long)SEQ * SEQ);

    // 5) logsumexp over query axis
    col_lse<<<dim3(SEQ / 32, BATCH), dim3(32, 8)>>>(pS, pL);

    // 6) O = exp(S - L) @ V
    gemm_bf16_pv<<<dim3(DIM / 128, SEQ / 128, BATCH), 256, SM_TOTAL>>>(pS, pL, Vth, Vtl, out);
}

// round 9
// speedup vs baseline: 1.3212x; 1.3212x over previous
#include <cuda_runtime.h>
#include <cuda_bf16.h>
#include <stdint.h>
#include <math.h>

#define BATCH 4
#define SEQ   4096
#define DIM   512
#define MQKV  (BATCH * SEQ)   // 16384

// ---------------- scratch (__device__ globals; no allocs allowed) -----------
__device__ __nv_bfloat16 g_xh[(size_t)MQKV * DIM], g_xl[(size_t)MQKV * DIM];
__device__ __nv_bfloat16 g_Wh[3 * DIM * DIM],      g_Wl[3 * DIM * DIM];
__device__ __nv_bfloat16 g_Qh[(size_t)MQKV * DIM], g_Ql[(size_t)MQKV * DIM];
__device__ __nv_bfloat16 g_Kh[(size_t)MQKV * DIM], g_Kl[(size_t)MQKV * DIM];
__device__ float         g_V [(size_t)MQKV * DIM];
__device__ __nv_bfloat16 g_Vth[(size_t)MQKV * DIM], g_Vtl[(size_t)MQKV * DIM];
__device__ float         g_S [(size_t)BATCH * SEQ * SEQ];   // 268 MB
__device__ __nv_bfloat16 g_Ph[(size_t)BATCH * SEQ * SEQ];   // 134 MB
__device__ __nv_bfloat16 g_Pl[(size_t)BATCH * SEQ * SEQ];   // 134 MB
__device__ float         g_L [BATCH * SEQ];

// ---------------- helpers ----------------------------------------------------
static __device__ __forceinline__ uint32_t smem_u32(const void* p){
    uint32_t a;
    asm("{ .reg .u64 t; cvta.to.shared.u64 t, %1; cvt.u32.u64 %0, t; }" : "=r"(a) : "l"(p));
    return a;
}
static __device__ __forceinline__ void ldsm4(uint32_t* r, uint32_t addr){
    asm volatile("ldmatrix.sync.aligned.m8n8.x4.shared.b16 {%0,%1,%2,%3}, [%4];"
        : "=r"(r[0]), "=r"(r[1]), "=r"(r[2]), "=r"(r[3]) : "r"(addr));
}
static __device__ __forceinline__ void ldsm2(uint32_t* r, uint32_t addr){
    asm volatile("ldmatrix.sync.aligned.m8n8.x2.shared.b16 {%0,%1}, [%2];"
        : "=r"(r[0]), "=r"(r[1]) : "r"(addr));
}
static __device__ __forceinline__ void mma16816(float* c, const uint32_t* a, const uint32_t* b){
    asm volatile("mma.sync.aligned.m16n8k16.row.col.f32.bf16.bf16.f32 "
        "{%0,%1,%2,%3}, {%4,%5,%6,%7}, {%8,%9}, {%0,%1,%2,%3};"
        : "+f"(c[0]), "+f"(c[1]), "+f"(c[2]), "+f"(c[3])
        : "r"(a[0]), "r"(a[1]), "r"(a[2]), "r"(a[3]), "r"(b[0]), "r"(b[1]));
}
static __device__ __forceinline__ void cpasync16(uint32_t dst, const void* src){
    asm volatile("cp.async.ca.shared.global [%0], [%1], 16;" :: "r"(dst), "l"(src));
}
#define CP_COMMIT() asm volatile("cp.async.commit_group;" ::: "memory")
#define CP_WAIT0()  asm volatile("cp.async.wait_group 0;" ::: "memory")

// ---------------- smem plan --------------------------------------------------
// 4 tiles per stage, each 128 rows x 32 bf16, row stride padded to 80 B
// (20*r mod 32 covers all banks -> conflict-free ldmatrix).
#define ROWB   80
#define TILE_B (128 * ROWB)          // 10240
#define T_AHI  0
#define T_ALO  (1 * TILE_B)
#define T_BHI  (2 * TILE_B)
#define T_BLO  (3 * TILE_B)
#define STAGE_B (4 * TILE_B)         // 40960
#define SM_TOTAL (2 * STAGE_B)       // 81920

// async bf16 tile loader: 128 rows x 32 cols from row-major K-contiguous global.
static __device__ __forceinline__ void ldB_async(uint32_t tile, const __nv_bfloat16* __restrict__ G,
                                                 int rowbase, long long ld, int k0, int tid){
    const int row = tid >> 1, half = tid & 1;
    const __nv_bfloat16* src = G + (size_t)(rowbase + row) * ld + k0 + half * 16;
    const uint32_t dst = tile + row * ROWB + half * 32;
    cpasync16(dst,      src);
    cpasync16(dst + 16, src + 8);
}

// ---------------- bf16 3-split tensor GEMM NT --------------------------------
// C[M,Nc] = (Ah+Al)[M,K] @ (Bh+Bl)[Nc,K]^T (+bias). mode 0: fp32 out; mode 1:
// split out to Chi/Clo. 128x128 CTA tile, 8 warps of 64x32, K-chunk 32.
__global__ __launch_bounds__(256, 1) void gemm_bf16_nt(
    const __nv_bfloat16* __restrict__ Ahg, const __nv_bfloat16* __restrict__ Alg,
    const __nv_bfloat16* __restrict__ Bhg, const __nv_bfloat16* __restrict__ Blg,
    const float* __restrict__ bias,
    float* __restrict__ Cf, __nv_bfloat16* __restrict__ Chi, __nv_bfloat16* __restrict__ Clo,
    int K, int Nc, int mode, long long sA, long long sB, long long sC)
{
    extern __shared__ char smem[];
    const int tid = threadIdx.x, wid = tid >> 5, lane = tid & 31;
    const int browG = blockIdx.y * 128, bcolG = blockIdx.x * 128;
    const int z = blockIdx.z;

    const __nv_bfloat16* Ah = Ahg + (long long)z * sA;
    const __nv_bfloat16* Al = Alg + (long long)z * sA;
    const __nv_bfloat16* Bh = Bhg + (long long)z * sB;
    const __nv_bfloat16* Bl = Blg + (long long)z * sB;

    float acc[4][4][4];
    #pragma unroll
    for (int i = 0; i < 4; i++)
        #pragma unroll
        for (int j = 0; j < 4; j++)
            #pragma unroll
            for (int k = 0; k < 4; k++) acc[i][j][k] = 0.f;

    const uint32_t sbase = smem_u32(smem);

    // prologue: chunk 0 -> stage 0 (async)
    ldB_async(sbase + T_AHI, Ah, browG, K, 0, tid);
    ldB_async(sbase + T_ALO, Al, browG, K, 0, tid);
    ldB_async(sbase + T_BHI, Bh, bcolG, K, 0, tid);
    ldB_async(sbase + T_BLO, Bl, bcolG, K, 0, tid);
    CP_COMMIT();
    CP_WAIT0();
    __syncthreads();

    const int wm = (wid & 1) * 64;
    const int wn = (wid >> 1) * 32;
    const uint32_t aoffA = (uint32_t)((wm + (lane & 15)) * ROWB + (lane >> 4) * 16);
    const uint32_t aoffB = (uint32_t)((wn + (lane & 7)) * ROWB + ((lane >> 3) & 1) * 16);

    const int nch = K >> 5;
    for (int c = 0; c < nch; c++){
        const int p = c & 1;
        if (c + 1 < nch){
            const uint32_t st = sbase + (p ^ 1) * STAGE_B;
            const int k0 = (c + 1) << 5;
            ldB_async(st + T_AHI, Ah, browG, K, k0, tid);
            ldB_async(st + T_ALO, Al, browG, K, k0, tid);
            ldB_async(st + T_BHI, Bh, bcolG, K, k0, tid);
            ldB_async(st + T_BLO, Bl, bcolG, K, k0, tid);
            CP_COMMIT();
        }
        const uint32_t sb = sbase + p * STAGE_B;
        #pragma unroll
        for (int ks = 0; ks < 2; ks++){
            const uint32_t kb = ks * 32;
            uint32_t ah[4][4], al[4][4], bh[4][2], bl[4][2];
            #pragma unroll
            for (int mt = 0; mt < 4; mt++){
                ldsm4(ah[mt], sb + T_AHI + aoffA + mt * (16 * ROWB) + kb);
                ldsm4(al[mt], sb + T_ALO + aoffA + mt * (16 * ROWB) + kb);
            }
            #pragma unroll
            for (int nt = 0; nt < 4; nt++){
                ldsm2(bh[nt], sb + T_BHI + aoffB + nt * (8 * ROWB) + kb);
                ldsm2(bl[nt], sb + T_BLO + aoffB + nt * (8 * ROWB) + kb);
            }
            #pragma unroll
            for (int mt = 0; mt < 4; mt++)
                #pragma unroll
                for (int nt = 0; nt < 4; nt++){
                    mma16816(acc[mt][nt], ah[mt], bh[nt]);
                    mma16816(acc[mt][nt], ah[mt], bl[nt]);
                    mma16816(acc[mt][nt], al[mt], bh[nt]);
                }
        }
        CP_WAIT0();
        __syncthreads();
    }

    // epilogue
    const int g = lane >> 2, t = lane & 3;
    #pragma unroll
    for (int mt = 0; mt < 4; mt++){
        #pragma unroll
        for (int nt = 0; nt < 4; nt++){
            const long long r  = browG + wm + mt * 16 + g;
            const int       cc = bcolG + wn + nt * 8 + t * 2;
            const float* a = acc[mt][nt];
            const float b0 = bias ? bias[cc]     : 0.f;
            const float b1 = bias ? bias[cc + 1] : 0.f;
            const float v0 = a[0] + b0, v1 = a[1] + b1;
            const float v2 = a[2] + b0, v3 = a[3] + b1;
            if (mode == 0){
                float* Cz = Cf + (long long)z * sC;
                *(float2*)(Cz + r * (long long)Nc + cc)       = make_float2(v0, v1);
                *(float2*)(Cz + (r + 8) * (long long)Nc + cc) = make_float2(v2, v3);
            } else {
                __nv_bfloat16 h0 = __float2bfloat16(v0), h1 = __float2bfloat16(v1);
                __nv_bfloat16 h2 = __float2bfloat16(v2), h3 = __float2bfloat16(v3);
                __nv_bfloat162 hh0; hh0.x = h0; hh0.y = h1;
                __nv_bfloat162 hh1; hh1.x = h2; hh1.y = h3;
                __nv_bfloat162 ll0;
                ll0.x = __float2bfloat16(v0 - __bfloat162float(h0));
                ll0.y = __float2bfloat16(v1 - __bfloat162float(h1));
                __nv_bfloat162 ll1;
                ll1.x = __float2bfloat16(v2 - __bfloat162float(h2));
                ll1.y = __float2bfloat16(v3 - __bfloat162float(h3));
                *(__nv_bfloat162*)(Chi + r * (long long)Nc + cc)       = hh0;
                *(__nv_bfloat162*)(Chi + (r + 8) * (long long)Nc + cc) = hh1;
                *(__nv_bfloat162*)(Clo + r * (long long)Nc + cc)       = ll0;
                *(__nv_bfloat162*)(Clo + (r + 8) * (long long)Nc + cc) = ll1;
            }
        }
    }
}

// ---------------- small kernels ----------------------------------------------
__global__ void split_pair(const float* __restrict__ x, __nv_bfloat16* __restrict__ hi,
                           __nv_bfloat16* __restrict__ lo, long long n)
{
    long long i = (long long)blockIdx.x * blockDim.x + threadIdx.x;
    const long long stride = (long long)gridDim.x * blockDim.x;
    for (; i < n; i += stride){
        const float v = x[i];
        __nv_bfloat16 h = __float2bfloat16(v);
        hi[i] = h;
        lo[i] = __float2bfloat16(v - __bfloat162float(h));
    }
}

__global__ void transpose_split(const float* __restrict__ V,
                                __nv_bfloat16* __restrict__ Th, __nv_bfloat16* __restrict__ Tl)
{
    __shared__ float t[32][33];
    const int b = blockIdx.z;
    const int d0 = blockIdx.x * 32, k0 = blockIdx.y * 32;
    const float* Vb = V + (size_t)b * SEQ * DIM;
    #pragma unroll
    for (int r = 0; r < 4; r++)
        t[threadIdx.y + 8 * r][threadIdx.x] =
            Vb[(size_t)(k0 + threadIdx.y + 8 * r) * DIM + d0 + threadIdx.x];
    __syncthreads();
    __nv_bfloat16* Thb = Th + (size_t)b * DIM * SEQ;
    __nv_bfloat16* Tlb = Tl + (size_t)b * DIM * SEQ;
    #pragma unroll
    for (int r = 0; r < 4; r++){
        const float v = t[threadIdx.x][threadIdx.y + 8 * r];
        __nv_bfloat16 h = __float2bfloat16(v);
        const size_t idx = (size_t)(d0 + threadIdx.y + 8 * r) * SEQ + k0 + threadIdx.x;
        Thb[idx] = h;
        Tlb[idx] = __float2bfloat16(v - __bfloat162float(h));
    }
}

__global__ void col_lse(const float* __restrict__ S, float* __restrict__ L)
{
    const int b = blockIdx.y;
    const int k = blockIdx.x * 32 + threadIdx.x;
    const float* Sb = S + (size_t)b * SEQ * SEQ;

    float m = -INFINITY, s = 0.f;
    for (int q = threadIdx.y; q < SEQ; q += 8) {
        const float v = Sb[(size_t)q * SEQ + k];
        const float mn = fmaxf(m, v);
        s = s * __expf(m - mn) + __expf(v - mn);
        m = mn;
    }
    __shared__ float sm[8][33], ss[8][33];
    sm[threadIdx.y][threadIdx.x] = m;
    ss[threadIdx.y][threadIdx.x] = s;
    __syncthreads();
    if (threadIdx.y == 0) {
        float M = m, Sa = s;
        #pragma unroll
        for (int t = 1; t < 8; t++) {
            const float m2 = sm[t][threadIdx.x], s2 = ss[t][threadIdx.x];
            const float Mn = fmaxf(M, m2);
            Sa = Sa * __expf(M - Mn) + s2 * __expf(m2 - Mn);
            M = Mn;
        }
        L[b * SEQ + k] = M + __logf(Sa);
    }
}

// P = exp(S - L[k]) split to bf16 hi/lo, one pass over the whole S tensor.
__global__ void compute_p(const float* __restrict__ S, const float* __restrict__ L,
                          __nv_bfloat16* __restrict__ Ph, __nv_bfloat16* __restrict__ Pl)
{
    const long long n4 = (long long)BATCH * SEQ * SEQ / 4;
    long long i = (long long)blockIdx.x * blockDim.x + threadIdx.x;
    const long long stride = (long long)gridDim.x * blockDim.x;
    for (; i < n4; i += stride){
        const long long e = i * 4;
        const int b = (int)(e / ((long long)SEQ * SEQ));
        const int k = (int)(e % SEQ);
        const float4 sv = *(const float4*)(S + e);
        const float4 lv = *(const float4*)(L + b * SEQ + k);
        const float p0 = __expf(sv.x - lv.x), p1 = __expf(sv.y - lv.y);
        const float p2 = __expf(sv.z - lv.z), p3 = __expf(sv.w - lv.w);
        const __nv_bfloat16 h0 = __float2bfloat16(p0), h1 = __float2bfloat16(p1);
        const __nv_bfloat16 h2 = __float2bfloat16(p2), h3 = __float2bfloat16(p3);
        __nv_bfloat162 hA; hA.x = h0; hA.y = h1;
        __nv_bfloat162 hB; hB.x = h2; hB.y = h3;
        __nv_bfloat162 lA;
        lA.x = __float2bfloat16(p0 - __bfloat162float(h0));
        lA.y = __float2bfloat16(p1 - __bfloat162float(h1));
        __nv_bfloat162 lB;
        lB.x = __float2bfloat16(p2 - __bfloat162float(h2));
        lB.y = __float2bfloat16(p3 - __bfloat162float(h3));
        *(__nv_bfloat162*)(Ph + e)     = hA;
        *(__nv_bfloat162*)(Ph + e + 2) = hB;
        *(__nv_bfloat162*)(Pl + e)     = lA;
        *(__nv_bfloat162*)(Pl + e + 2) = lB;
    }
}

// ---------------- launcher ---------------------------------------------------
extern "C" void kernel_launch(void* const* d_in, const int* in_sizes, int n_in,
                              void* d_out, int out_size)
{
    const float* x  = (const float*)d_in[0];
    const float* Wq = (const float*)d_in[1];
    const float* bq = (const float*)d_in[2];
    const float* Wk = (const float*)d_in[3];
    const float* bk = (const float*)d_in[4];
    const float* Wv = (const float*)d_in[5];
    const float* bv = (const float*)d_in[6];
    float* out = (float*)d_out;

    __nv_bfloat16 *xh, *xl, *Wh, *Wl, *Qh, *Ql, *Kh, *Kl, *Vth, *Vtl, *Ph, *Pl;
    float *Vf, *pS, *pL;
    cudaGetSymbolAddress((void**)&xh,  g_xh);  cudaGetSymbolAddress((void**)&xl,  g_xl);
    cudaGetSymbolAddress((void**)&Wh,  g_Wh);  cudaGetSymbolAddress((void**)&Wl,  g_Wl);
    cudaGetSymbolAddress((void**)&Qh,  g_Qh);  cudaGetSymbolAddress((void**)&Ql,  g_Ql);
    cudaGetSymbolAddress((void**)&Kh,  g_Kh);  cudaGetSymbolAddress((void**)&Kl,  g_Kl);
    cudaGetSymbolAddress((void**)&Vth, g_Vth); cudaGetSymbolAddress((void**)&Vtl, g_Vtl);
    cudaGetSymbolAddress((void**)&Ph,  g_Ph);  cudaGetSymbolAddress((void**)&Pl,  g_Pl);
    cudaGetSymbolAddress((void**)&Vf,  g_V);
    cudaGetSymbolAddress((void**)&pS,  g_S);   cudaGetSymbolAddress((void**)&pL,  g_L);

    cudaFuncSetAttribute(gemm_bf16_nt, cudaFuncAttributeMaxDynamicSharedMemorySize, SM_TOTAL);

    // 1) hi/lo splits
    split_pair<<<1024, 256>>>(x,  xh, xl, (long long)MQKV * DIM);
    split_pair<<<256, 256>>>(Wq, Wh + 0 * DIM * DIM, Wl + 0 * DIM * DIM, (long long)DIM * DIM);
    split_pair<<<256, 256>>>(Wk, Wh + 1 * DIM * DIM, Wl + 1 * DIM * DIM, (long long)DIM * DIM);
    split_pair<<<256, 256>>>(Wv, Wh + 2 * DIM * DIM, Wl + 2 * DIM * DIM, (long long)DIM * DIM);

    // 2) projections
    {
        dim3 g(DIM / 128, MQKV / 128, 1);
        gemm_bf16_nt<<<g, 256, SM_TOTAL>>>(xh, xl, Wh + 0 * DIM * DIM, Wl + 0 * DIM * DIM, bq,
                                           nullptr, Qh, Ql, DIM, DIM, 1, 0, 0, 0);
        gemm_bf16_nt<<<g, 256, SM_TOTAL>>>(xh, xl, Wh + 1 * DIM * DIM, Wl + 1 * DIM * DIM, bk,
                                           nullptr, Kh, Kl, DIM, DIM, 1, 0, 0, 0);
        gemm_bf16_nt<<<g, 256, SM_TOTAL>>>(xh, xl, Wh + 2 * DIM * DIM, Wl + 2 * DIM * DIM, bv,
                                           Vf, nullptr, nullptr, DIM, DIM, 0, 0, 0, 0);
    }

    // 3) V -> Vt with split
    transpose_split<<<dim3(DIM / 32, SEQ / 32, BATCH), dim3(32, 8)>>>(Vf, Vth, Vtl);

    // 4) S = Q @ K^T (batched)
    gemm_bf16_nt<<<dim3(SEQ / 128, SEQ / 128, BATCH), 256, SM_TOTAL>>>(
        Qh, Ql, Kh, Kl, nullptr, pS, nullptr, nullptr,
        DIM, SEQ, 0, (long long)SEQ * DIM, (long long)SEQ * DIM, (long long)SEQ * SEQ);

    // 5) logsumexp over query axis
    col_lse<<<dim3(SEQ / 32, BATCH), dim3(32, 8)>>>(pS, pL);

    // 6) P = exp(S - L), bf16 hi/lo, single pass
    compute_p<<<2048, 256>>>(pS, pL, Ph, Pl);

    // 7) O = P @ Vt^T  (pure NT GEMM, same kernel)
    gemm_bf16_nt<<<dim3(DIM / 128, SEQ / 128, BATCH), 256, SM_TOTAL>>>(
        Ph, Pl, Vth, Vtl, nullptr, out, nullptr, nullptr,
        SEQ, DIM, 0, (long long)SEQ * SEQ, (long long)DIM * SEQ, (long long)SEQ * DIM);
}

// round 13
// speedup vs baseline: 1.7500x; 1.3245x over previous
#include <cuda_runtime.h>
#include <cuda_bf16.h>
#include <cuda_fp16.h>
#include <stdint.h>
#include <math.h>

#define BATCH 4
#define SEQ   4096
#define DIM   512
#define MQKV  (BATCH * SEQ)   // 16384

// ---------------- scratch (__device__ globals; no allocs allowed) -----------
__device__ __nv_bfloat16 g_xh[(size_t)MQKV * DIM], g_xl[(size_t)MQKV * DIM];
__device__ __nv_bfloat16 g_Wh[3 * DIM * DIM],      g_Wl[3 * DIM * DIM];
__device__ __nv_bfloat16 g_Qh[(size_t)MQKV * DIM], g_Ql[(size_t)MQKV * DIM];
__device__ __nv_bfloat16 g_Kh[(size_t)MQKV * DIM], g_Kl[(size_t)MQKV * DIM];
__device__ float         g_V [(size_t)MQKV * DIM];
__device__ __half        g_Vth[(size_t)MQKV * DIM];          // fp16, single term
__device__ float         g_S [(size_t)BATCH * SEQ * SEQ];    // 268 MB
__device__ __half        g_Ph[(size_t)BATCH * SEQ * SEQ];    // 134 MB, single term
__device__ float         g_L [BATCH * SEQ];

// ---------------- helpers ----------------------------------------------------
static __device__ __forceinline__ uint32_t smem_u32(const void* p){
    uint32_t a;
    asm("{ .reg .u64 t; cvta.to.shared.u64 t, %1; cvt.u32.u64 %0, t; }" : "=r"(a) : "l"(p));
    return a;
}
static __device__ __forceinline__ void ldsm4(uint32_t* r, uint32_t addr){
    asm volatile("ldmatrix.sync.aligned.m8n8.x4.shared.b16 {%0,%1,%2,%3}, [%4];"
        : "=r"(r[0]), "=r"(r[1]), "=r"(r[2]), "=r"(r[3]) : "r"(addr));
}
static __device__ __forceinline__ void ldsm2(uint32_t* r, uint32_t addr){
    asm volatile("ldmatrix.sync.aligned.m8n8.x2.shared.b16 {%0,%1}, [%2];"
        : "=r"(r[0]), "=r"(r[1]) : "r"(addr));
}
static __device__ __forceinline__ void mma_bf16(float* c, const uint32_t* a, const uint32_t* b){
    asm volatile("mma.sync.aligned.m16n8k16.row.col.f32.bf16.bf16.f32 "
        "{%0,%1,%2,%3}, {%4,%5,%6,%7}, {%8,%9}, {%0,%1,%2,%3};"
        : "+f"(c[0]), "+f"(c[1]), "+f"(c[2]), "+f"(c[3])
        : "r"(a[0]), "r"(a[1]), "r"(a[2]), "r"(a[3]), "r"(b[0]), "r"(b[1]));
}
static __device__ __forceinline__ void mma_f16(float* c, const uint32_t* a, const uint32_t* b){
    asm volatile("mma.sync.aligned.m16n8k16.row.col.f32.f16.f16.f32 "
        "{%0,%1,%2,%3}, {%4,%5,%6,%7}, {%8,%9}, {%0,%1,%2,%3};"
        : "+f"(c[0]), "+f"(c[1]), "+f"(c[2]), "+f"(c[3])
        : "r"(a[0]), "r"(a[1]), "r"(a[2]), "r"(a[3]), "r"(b[0]), "r"(b[1]));
}
static __device__ __forceinline__ void cpasync16(uint32_t dst, const void* src){
    asm volatile("cp.async.ca.shared.global [%0], [%1], 16;" :: "r"(dst), "l"(src));
}
#define CP_COMMIT() asm volatile("cp.async.commit_group;" ::: "memory")
#define CP_WAIT0()  asm volatile("cp.async.wait_group 0;" ::: "memory")

// ---------------- smem plan --------------------------------------------------
// Tiles: 128 rows x 32 b16, row stride 80 B (20r mod 32 covers all banks).
#define ROWB   80
#define TILE_B (128 * ROWB)          // 10240
#define T_AHI  0
#define T_ALO  (1 * TILE_B)
#define T_BHI  (2 * TILE_B)
#define T_BLO  (3 * TILE_B)
#define STAGE_B (4 * TILE_B)         // 40960 (bf16 3-split GEMM)
#define SM_TOTAL (2 * STAGE_B)       // 81920
#define STAGE_PV (2 * TILE_B)        // 20480 (fp16 PV GEMM: A + B)
#define SM_PV    (2 * STAGE_PV)      // 40960

// async b16 tile loader: 128 rows x 32 cols from row-major K-contiguous global.
template<typename T>
static __device__ __forceinline__ void ldB_async(uint32_t tile, const T* __restrict__ G,
                                                 int rowbase, long long ld, int k0, int tid){
    const int row = tid >> 1, half_ = tid & 1;
    const T* src = G + (size_t)(rowbase + row) * ld + k0 + half_ * 16;
    const uint32_t dst = tile + row * ROWB + half_ * 32;
    cpasync16(dst,      src);
    cpasync16(dst + 16, src + 8);
}

// ---------------- bf16 3-split tensor GEMM NT (proven: rel_err 2.7e-5) -------
// C[M,Nc] = (Ah+Al)[M,K] @ (Bh+Bl)[Nc,K]^T (+bias). mode 0: fp32 out; mode 1:
// split out to Chi/Clo. 128x128 CTA tile, 8 warps of 64x32, K-chunk 32.
__global__ __launch_bounds__(256, 1) void gemm_bf16_nt(
    const __nv_bfloat16* __restrict__ Ahg, const __nv_bfloat16* __restrict__ Alg,
    const __nv_bfloat16* __restrict__ Bhg, const __nv_bfloat16* __restrict__ Blg,
    const float* __restrict__ bias,
    float* __restrict__ Cf, __nv_bfloat16* __restrict__ Chi, __nv_bfloat16* __restrict__ Clo,
    int K, int Nc, int mode, long long sA, long long sB, long long sC)
{
    extern __shared__ char smem[];
    const int tid = threadIdx.x, wid = tid >> 5, lane = tid & 31;
    const int browG = blockIdx.y * 128, bcolG = blockIdx.x * 128;
    const int z = blockIdx.z;

    const __nv_bfloat16* Ah = Ahg + (long long)z * sA;
    const __nv_bfloat16* Al = Alg + (long long)z * sA;
    const __nv_bfloat16* Bh = Bhg + (long long)z * sB;
    const __nv_bfloat16* Bl = Blg + (long long)z * sB;

    float acc[4][4][4];
    #pragma unroll
    for (int i = 0; i < 4; i++)
        #pragma unroll
        for (int j = 0; j < 4; j++)
            #pragma unroll
            for (int k = 0; k < 4; k++) acc[i][j][k] = 0.f;

    const uint32_t sbase = smem_u32(smem);

    ldB_async(sbase + T_AHI, Ah, browG, K, 0, tid);
    ldB_async(sbase + T_ALO, Al, browG, K, 0, tid);
    ldB_async(sbase + T_BHI, Bh, bcolG, K, 0, tid);
    ldB_async(sbase + T_BLO, Bl, bcolG, K, 0, tid);
    CP_COMMIT();
    CP_WAIT0();
    __syncthreads();

    const int wm = (wid & 1) * 64;
    const int wn = (wid >> 1) * 32;
    const uint32_t aoffA = (uint32_t)((wm + (lane & 15)) * ROWB + (lane >> 4) * 16);
    const uint32_t aoffB = (uint32_t)((wn + (lane & 7)) * ROWB + ((lane >> 3) & 1) * 16);

    const int nch = K >> 5;
    for (int c = 0; c < nch; c++){
        const int p = c & 1;
        if (c + 1 < nch){
            const uint32_t st = sbase + (p ^ 1) * STAGE_B;
            const int k0 = (c + 1) << 5;
            ldB_async(st + T_AHI, Ah, browG, K, k0, tid);
            ldB_async(st + T_ALO, Al, browG, K, k0, tid);
            ldB_async(st + T_BHI, Bh, bcolG, K, k0, tid);
            ldB_async(st + T_BLO, Bl, bcolG, K, k0, tid);
            CP_COMMIT();
        }
        const uint32_t sb = sbase + p * STAGE_B;
        #pragma unroll
        for (int ks = 0; ks < 2; ks++){
            const uint32_t kb = ks * 32;
            uint32_t ah[4][4], al[4][4], bh[4][2], bl[4][2];
            #pragma unroll
            for (int mt = 0; mt < 4; mt++){
                ldsm4(ah[mt], sb + T_AHI + aoffA + mt * (16 * ROWB) + kb);
                ldsm4(al[mt], sb + T_ALO + aoffA + mt * (16 * ROWB) + kb);
            }
            #pragma unroll
            for (int nt = 0; nt < 4; nt++){
                ldsm2(bh[nt], sb + T_BHI + aoffB + nt * (8 * ROWB) + kb);
                ldsm2(bl[nt], sb + T_BLO + aoffB + nt * (8 * ROWB) + kb);
            }
            #pragma unroll
            for (int mt = 0; mt < 4; mt++)
                #pragma unroll
                for (int nt = 0; nt < 4; nt++){
                    mma_bf16(acc[mt][nt], ah[mt], bh[nt]);
                    mma_bf16(acc[mt][nt], ah[mt], bl[nt]);
                    mma_bf16(acc[mt][nt], al[mt], bh[nt]);
                }
        }
        CP_WAIT0();
        __syncthreads();
    }

    const int g = lane >> 2, t = lane & 3;
    #pragma unroll
    for (int mt = 0; mt < 4; mt++){
        #pragma unroll
        for (int nt = 0; nt < 4; nt++){
            const long long r  = browG + wm + mt * 16 + g;
            const int       cc = bcolG + wn + nt * 8 + t * 2;
            const float* a = acc[mt][nt];
            const float b0 = bias ? bias[cc]     : 0.f;
            const float b1 = bias ? bias[cc + 1] : 0.f;
            const float v0 = a[0] + b0, v1 = a[1] + b1;
            const float v2 = a[2] + b0, v3 = a[3] + b1;
            if (mode == 0){
                float* Cz = Cf + (long long)z * sC;
                *(float2*)(Cz + r * (long long)Nc + cc)       = make_float2(v0, v1);
                *(float2*)(Cz + (r + 8) * (long long)Nc + cc) = make_float2(v2, v3);
            } else {
                __nv_bfloat16 h0 = __float2bfloat16(v0), h1 = __float2bfloat16(v1);
                __nv_bfloat16 h2 = __float2bfloat16(v2), h3 = __float2bfloat16(v3);
                __nv_bfloat162 hh0; hh0.x = h0; hh0.y = h1;
                __nv_bfloat162 hh1; hh1.x = h2; hh1.y = h3;
                __nv_bfloat162 ll0;
                ll0.x = __float2bfloat16(v0 - __bfloat162float(h0));
                ll0.y = __float2bfloat16(v1 - __bfloat162float(h1));
                __nv_bfloat162 ll1;
                ll1.x = __float2bfloat16(v2 - __bfloat162float(h2));
                ll1.y = __float2bfloat16(v3 - __bfloat162float(h3));
                *(__nv_bfloat162*)(Chi + r * (long long)Nc + cc)       = hh0;
                *(__nv_bfloat162*)(Chi + (r + 8) * (long long)Nc + cc) = hh1;
                *(__nv_bfloat162*)(Clo + r * (long long)Nc + cc)       = ll0;
                *(__nv_bfloat162*)(Clo + (r + 8) * (long long)Nc + cc) = ll1;
            }
        }
    }
}

// ---------------- fp16 single-term PV GEMM NT --------------------------------
// O[q,d] = P[q,k] @ Vt[d,k]^T. 1 MMA per K16 step. 2 tiles/stage, 2 CTAs/SM.
__global__ __launch_bounds__(256, 2) void gemm_pv_f16(
    const __half* __restrict__ Pg, const __half* __restrict__ Vg,
    float* __restrict__ O)
{
    extern __shared__ char smem[];
    const int tid = threadIdx.x, wid = tid >> 5, lane = tid & 31;
    const int browG = blockIdx.y * 128, bcolG = blockIdx.x * 128;
    const int z = blockIdx.z;

    const __half* A = Pg + (size_t)z * SEQ * SEQ;
    const __half* B = Vg + (size_t)z * DIM * SEQ;
    float* Ob = O + (size_t)z * SEQ * DIM;

    float acc[4][4][4];
    #pragma unroll
    for (int i = 0; i < 4; i++)
        #pragma unroll
        for (int j = 0; j < 4; j++)
            #pragma unroll
            for (int k = 0; k < 4; k++) acc[i][j][k] = 0.f;

    const uint32_t sbase = smem_u32(smem);

    ldB_async(sbase + 0,      A, browG, SEQ, 0, tid);
    ldB_async(sbase + TILE_B, B, bcolG, SEQ, 0, tid);
    CP_COMMIT();
    CP_WAIT0();
    __syncthreads();

    const int wm = (wid & 1) * 64;
    const int wn = (wid >> 1) * 32;
    const uint32_t aoffA = (uint32_t)((wm + (lane & 15)) * ROWB + (lane >> 4) * 16);
    const uint32_t aoffB = (uint32_t)((wn + (lane & 7)) * ROWB + ((lane >> 3) & 1) * 16);

    const int nch = SEQ >> 5;   // 128
    for (int c = 0; c < nch; c++){
        const int p = c & 1;
        if (c + 1 < nch){
            const uint32_t st = sbase + (p ^ 1) * STAGE_PV;
            const int k0 = (c + 1) << 5;
            ldB_async(st + 0,      A, browG, SEQ, k0, tid);
            ldB_async(st + TILE_B, B, bcolG, SEQ, k0, tid);
            CP_COMMIT();
        }
        const uint32_t sb = sbase + p * STAGE_PV;
        #pragma unroll
        for (int ks = 0; ks < 2; ks++){
            const uint32_t kb = ks * 32;
            uint32_t ah[4][4], bh[4][2];
            #pragma unroll
            for (int mt = 0; mt < 4; mt++)
                ldsm4(ah[mt], sb + 0 + aoffA + mt * (16 * ROWB) + kb);
            #pragma unroll
            for (int nt = 0; nt < 4; nt++)
                ldsm2(bh[nt], sb + TILE_B + aoffB + nt * (8 * ROWB) + kb);
            #pragma unroll
            for (int mt = 0; mt < 4; mt++)
                #pragma unroll
                for (int nt = 0; nt < 4; nt++)
                    mma_f16(acc[mt][nt], ah[mt], bh[nt]);
        }
        CP_WAIT0();
        __syncthreads();
    }

    const int g = lane >> 2, t = lane & 3;
    #pragma unroll
    for (int mt = 0; mt < 4; mt++)
        #pragma unroll
        for (int nt = 0; nt < 4; nt++){
            const long long r  = browG + wm + mt * 16 + g;
            const int       cc = bcolG + wn + nt * 8 + t * 2;
            const float* a = acc[mt][nt];
            *(float2*)(Ob + r * (long long)DIM + cc)       = make_float2(a[0], a[1]);
            *(float2*)(Ob + (r + 8) * (long long)DIM + cc) = make_float2(a[2], a[3]);
        }
}

// ---------------- small kernels ----------------------------------------------
__global__ void split_pair(const float* __restrict__ x, __nv_bfloat16* __restrict__ hi,
                           __nv_bfloat16* __restrict__ lo, long long n)
{
    long long i = (long long)blockIdx.x * blockDim.x + threadIdx.x;
    const long long stride = (long long)gridDim.x * blockDim.x;
    for (; i < n; i += stride){
        const float v = x[i];
        __nv_bfloat16 h = __float2bfloat16(v);
        hi[i] = h;
        lo[i] = __float2bfloat16(v - __bfloat162float(h));
    }
}

__global__ void transpose_h(const float* __restrict__ V, __half* __restrict__ Th)
{
    __shared__ float t[32][33];
    const int b = blockIdx.z;
    const int d0 = blockIdx.x * 32, k0 = blockIdx.y * 32;
    const float* Vb = V + (size_t)b * SEQ * DIM;
    #pragma unroll
    for (int r = 0; r < 4; r++)
        t[threadIdx.y + 8 * r][threadIdx.x] =
            Vb[(size_t)(k0 + threadIdx.y + 8 * r) * DIM + d0 + threadIdx.x];
    __syncthreads();
    __half* Thb = Th + (size_t)b * DIM * SEQ;
    #pragma unroll
    for (int r = 0; r < 4; r++){
        const float v = t[threadIdx.x][threadIdx.y + 8 * r];
        Thb[(size_t)(d0 + threadIdx.y + 8 * r) * SEQ + k0 + threadIdx.x] = __float2half(v);
    }
}

__global__ void col_lse(const float* __restrict__ S, float* __restrict__ L)
{
    const int b = blockIdx.y;
    const int k = blockIdx.x * 32 + threadIdx.x;
    const float* Sb = S + (size_t)b * SEQ * SEQ;

    float m = -INFINITY, s = 0.f;
    for (int q = threadIdx.y; q < SEQ; q += 8) {
        const float v = Sb[(size_t)q * SEQ + k];
        const float mn = fmaxf(m, v);
        s = s * __expf(m - mn) + __expf(v - mn);
        m = mn;
    }
    __shared__ float sm[8][33], ss[8][33];
    sm[threadIdx.y][threadIdx.x] = m;
    ss[threadIdx.y][threadIdx.x] = s;
    __syncthreads();
    if (threadIdx.y == 0) {
        float M = m, Sa = s;
        #pragma unroll
        for (int t = 1; t < 8; t++) {
            const float m2 = sm[t][threadIdx.x], s2 = ss[t][threadIdx.x];
            const float Mn = fmaxf(M, m2);
            Sa = Sa * __expf(M - Mn) + s2 * __expf(m2 - Mn);
            M = Mn;
        }
        L[b * SEQ + k] = M + __logf(Sa);
    }
}

// P = exp(S - L[k]) -> fp16, one pass.
__global__ void compute_p(const float* __restrict__ S, const float* __restrict__ L,
                          __half* __restrict__ Ph)
{
    const long long n4 = (long long)BATCH * SEQ * SEQ / 4;
    long long i = (long long)blockIdx.x * blockDim.x + threadIdx.x;
    const long long stride = (long long)gridDim.x * blockDim.x;
    for (; i < n4; i += stride){
        const long long e = i * 4;
        const int b = (int)(e / ((long long)SEQ * SEQ));
        const int k = (int)(e % SEQ);
        const float4 sv = *(const float4*)(S + e);
        const float4 lv = *(const float4*)(L + b * SEQ + k);
        __half2 hA, hB;
        hA.x = __float2half(__expf(sv.x - lv.x));
        hA.y = __float2half(__expf(sv.y - lv.y));
        hB.x = __float2half(__expf(sv.z - lv.z));
        hB.y = __float2half(__expf(sv.w - lv.w));
        *(__half2*)(Ph + e)     = hA;
        *(__half2*)(Ph + e + 2) = hB;
    }
}

// ---------------- launcher ---------------------------------------------------
extern "C" void kernel_launch(void* const* d_in, const int* in_sizes, int n_in,
                              void* d_out, int out_size)
{
    const float* x  = (const float*)d_in[0];
    const float* Wq = (const float*)d_in[1];
    const float* bq = (const float*)d_in[2];
    const float* Wk = (const float*)d_in[3];
    const float* bk = (const float*)d_in[4];
    const float* Wv = (const float*)d_in[5];
    const float* bv = (const float*)d_in[6];
    float* out = (float*)d_out;

    __nv_bfloat16 *xh, *xl, *Wh, *Wl, *Qh, *Ql, *Kh, *Kl;
    __half *Vth, *Ph;
    float *Vf, *pS, *pL;
    cudaGetSymbolAddress((void**)&xh,  g_xh);  cudaGetSymbolAddress((void**)&xl,  g_xl);
    cudaGetSymbolAddress((void**)&Wh,  g_Wh);  cudaGetSymbolAddress((void**)&Wl,  g_Wl);
    cudaGetSymbolAddress((void**)&Qh,  g_Qh);  cudaGetSymbolAddress((void**)&Ql,  g_Ql);
    cudaGetSymbolAddress((void**)&Kh,  g_Kh);  cudaGetSymbolAddress((void**)&Kl,  g_Kl);
    cudaGetSymbolAddress((void**)&Vth, g_Vth); cudaGetSymbolAddress((void**)&Ph,  g_Ph);
    cudaGetSymbolAddress((void**)&Vf,  g_V);
    cudaGetSymbolAddress((void**)&pS,  g_S);   cudaGetSymbolAddress((void**)&pL,  g_L);

    cudaFuncSetAttribute(gemm_bf16_nt, cudaFuncAttributeMaxDynamicSharedMemorySize, SM_TOTAL);
    cudaFuncSetAttribute(gemm_pv_f16,  cudaFuncAttributeMaxDynamicSharedMemorySize, SM_PV);

    // 1) hi/lo splits
    split_pair<<<1024, 256>>>(x,  xh, xl, (long long)MQKV * DIM);
    split_pair<<<256, 256>>>(Wq, Wh + 0 * DIM * DIM, Wl + 0 * DIM * DIM, (long long)DIM * DIM);
    split_pair<<<256, 256>>>(Wk, Wh + 1 * DIM * DIM, Wl + 1 * DIM * DIM, (long long)DIM * DIM);
    split_pair<<<256, 256>>>(Wv, Wh + 2 * DIM * DIM, Wl + 2 * DIM * DIM, (long long)DIM * DIM);

    // 2) projections
    {
        dim3 g(DIM / 128, MQKV / 128, 1);
        gemm_bf16_nt<<<g, 256, SM_TOTAL>>>(xh, xl, Wh + 0 * DIM * DIM, Wl + 0 * DIM * DIM, bq,
                                           nullptr, Qh, Ql, DIM, DIM, 1, 0, 0, 0);
        gemm_bf16_nt<<<g, 256, SM_TOTAL>>>(xh, xl, Wh + 1 * DIM * DIM, Wl + 1 * DIM * DIM, bk,
                                           nullptr, Kh, Kl, DIM, DIM, 1, 0, 0, 0);
        gemm_bf16_nt<<<g, 256, SM_TOTAL>>>(xh, xl, Wh + 2 * DIM * DIM, Wl + 2 * DIM * DIM, bv,
                                           Vf, nullptr, nullptr, DIM, DIM, 0, 0, 0, 0);
    }

    // 3) V -> Vt (fp16)
    transpose_h<<<dim3(DIM / 32, SEQ / 32, BATCH), dim3(32, 8)>>>(Vf, Vth);

    // 4) S = Q @ K^T (batched, bf16 3-split: accuracy-critical)
    gemm_bf16_nt<<<dim3(SEQ / 128, SEQ / 128, BATCH), 256, SM_TOTAL>>>(
        Qh, Ql, Kh, Kl, nullptr, pS, nullptr, nullptr,
        DIM, SEQ, 0, (long long)SEQ * DIM, (long long)SEQ * DIM, (long long)SEQ * SEQ);

    // 5) logsumexp over query axis
    col_lse<<<dim3(SEQ / 32, BATCH), dim3(32, 8)>>>(pS, pL);

    // 6) P = exp(S - L), fp16, single pass
    compute_p<<<2048, 256>>>(pS, pL, Ph);

    // 7) O = P @ Vt^T  (fp16 single-term GEMM)
    gemm_pv_f16<<<dim3(DIM / 128, SEQ / 128, BATCH), 256, SM_PV>>>(Ph, Vth, out);
}

// round 17
// speedup vs baseline: 2.0185x; 1.1535x over previous
#include <cuda_runtime.h>
#include <cuda_bf16.h>
#include <cuda_fp16.h>
#include <stdint.h>
#include <math.h>

#define BATCH 4
#define SEQ   4096
#define DIM   512
#define MQKV  (BATCH * SEQ)   // 16384

// ---------------- scratch (__device__ globals; no allocs allowed) -----------
__device__ __nv_bfloat16 g_xh[(size_t)MQKV * DIM], g_xl[(size_t)MQKV * DIM];
__device__ __nv_bfloat16 g_Wh[3 * DIM * DIM],      g_Wl[3 * DIM * DIM];
__device__ __nv_bfloat16 g_Qh[(size_t)MQKV * DIM], g_Ql[(size_t)MQKV * DIM];
__device__ __nv_bfloat16 g_Kh[(size_t)MQKV * DIM], g_Kl[(size_t)MQKV * DIM];
__device__ float         g_V [(size_t)MQKV * DIM];
__device__ __half        g_Vth[(size_t)MQKV * DIM];          // fp16, single term
__device__ float         g_S [(size_t)BATCH * SEQ * SEQ];    // 268 MB
__device__ __half        g_Ph[(size_t)BATCH * SEQ * SEQ];    // 134 MB, single term
__device__ float         g_L [BATCH * SEQ];

// ---------------- helpers ----------------------------------------------------
static __device__ __forceinline__ uint32_t smem_u32(const void* p){
    uint32_t a;
    asm("{ .reg .u64 t; cvta.to.shared.u64 t, %1; cvt.u32.u64 %0, t; }" : "=r"(a) : "l"(p));
    return a;
}
static __device__ __forceinline__ void ldsm4(uint32_t* r, uint32_t addr){
    asm volatile("ldmatrix.sync.aligned.m8n8.x4.shared.b16 {%0,%1,%2,%3}, [%4];"
        : "=r"(r[0]), "=r"(r[1]), "=r"(r[2]), "=r"(r[3]) : "r"(addr));
}
static __device__ __forceinline__ void ldsm2(uint32_t* r, uint32_t addr){
    asm volatile("ldmatrix.sync.aligned.m8n8.x2.shared.b16 {%0,%1}, [%2];"
        : "=r"(r[0]), "=r"(r[1]) : "r"(addr));
}
static __device__ __forceinline__ void mma_bf16(float* c, const uint32_t* a, const uint32_t* b){
    asm volatile("mma.sync.aligned.m16n8k16.row.col.f32.bf16.bf16.f32 "
        "{%0,%1,%2,%3}, {%4,%5,%6,%7}, {%8,%9}, {%0,%1,%2,%3};"
        : "+f"(c[0]), "+f"(c[1]), "+f"(c[2]), "+f"(c[3])
        : "r"(a[0]), "r"(a[1]), "r"(a[2]), "r"(a[3]), "r"(b[0]), "r"(b[1]));
}
static __device__ __forceinline__ void mma_f16(float* c, const uint32_t* a, const uint32_t* b){
    asm volatile("mma.sync.aligned.m16n8k16.row.col.f32.f16.f16.f32 "
        "{%0,%1,%2,%3}, {%4,%5,%6,%7}, {%8,%9}, {%0,%1,%2,%3};"
        : "+f"(c[0]), "+f"(c[1]), "+f"(c[2]), "+f"(c[3])
        : "r"(a[0]), "r"(a[1]), "r"(a[2]), "r"(a[3]), "r"(b[0]), "r"(b[1]));
}
static __device__ __forceinline__ void cpasync16(uint32_t dst, const void* src){
    asm volatile("cp.async.ca.shared.global [%0], [%1], 16;" :: "r"(dst), "l"(src));
}
#define CP_COMMIT() asm volatile("cp.async.commit_group;" ::: "memory")
#define CP_WAIT0()  asm volatile("cp.async.wait_group 0;" ::: "memory")

// ---------------- smem plan --------------------------------------------------
// Tiles: 128 rows x 32 b16, row stride 80 B (20r mod 32 covers all banks).
#define ROWB   80
#define TILE_B (128 * ROWB)          // 10240
#define T_AHI  0
#define T_ALO  (1 * TILE_B)
#define T_BHI  (2 * TILE_B)
#define T_BLO  (3 * TILE_B)
#define STAGE_B (4 * TILE_B)         // 40960 (bf16 3-split GEMM)
#define SM_TOTAL (2 * STAGE_B)       // 81920
#define STAGE_PV (2 * TILE_B)        // 20480 (fp16 PV GEMM: A + B)
#define SM_PV    (2 * STAGE_PV)      // 40960

// async b16 tile loader: 128 rows x 32 cols from row-major K-contiguous global.
template<typename T>
static __device__ __forceinline__ void ldB_async(uint32_t tile, const T* __restrict__ G,
                                                 int rowbase, long long ld, int k0, int tid){
    const int row = tid >> 1, half_ = tid & 1;
    const T* src = G + (size_t)(rowbase + row) * ld + k0 + half_ * 16;
    const uint32_t dst = tile + row * ROWB + half_ * 32;
    cpasync16(dst,      src);
    cpasync16(dst + 16, src + 8);
}

// ---------------- bf16 3-split tensor GEMM NT --------------------------------
// C[M,Nc] = (Ah+Al)[M,K] @ (Bh+Bl)[Nc,K]^T (+bias). mode 0: fp32 out; mode 1:
// split out to Chi/Clo. 128x128 CTA tile, 8 warps of 64x32, K-chunk 32.
// A-fragments streamed per-mt (live regs ~110) -> 2 CTAs/SM.
__global__ __launch_bounds__(256, 2) void gemm_bf16_nt(
    const __nv_bfloat16* __restrict__ Ahg, const __nv_bfloat16* __restrict__ Alg,
    const __nv_bfloat16* __restrict__ Bhg, const __nv_bfloat16* __restrict__ Blg,
    const float* __restrict__ bias,
    float* __restrict__ Cf, __nv_bfloat16* __restrict__ Chi, __nv_bfloat16* __restrict__ Clo,
    int K, int Nc, int mode, long long sA, long long sB, long long sC)
{
    extern __shared__ char smem[];
    const int tid = threadIdx.x, wid = tid >> 5, lane = tid & 31;
    const int browG = blockIdx.y * 128, bcolG = blockIdx.x * 128;
    const int z = blockIdx.z;

    const __nv_bfloat16* Ah = Ahg + (long long)z * sA;
    const __nv_bfloat16* Al = Alg + (long long)z * sA;
    const __nv_bfloat16* Bh = Bhg + (long long)z * sB;
    const __nv_bfloat16* Bl = Blg + (long long)z * sB;

    float acc[4][4][4];
    #pragma unroll
    for (int i = 0; i < 4; i++)
        #pragma unroll
        for (int j = 0; j < 4; j++)
            #pragma unroll
            for (int k = 0; k < 4; k++) acc[i][j][k] = 0.f;

    const uint32_t sbase = smem_u32(smem);

    ldB_async(sbase + T_AHI, Ah, browG, K, 0, tid);
    ldB_async(sbase + T_ALO, Al, browG, K, 0, tid);
    ldB_async(sbase + T_BHI, Bh, bcolG, K, 0, tid);
    ldB_async(sbase + T_BLO, Bl, bcolG, K, 0, tid);
    CP_COMMIT();
    CP_WAIT0();
    __syncthreads();

    const int wm = (wid & 1) * 64;
    const int wn = (wid >> 1) * 32;
    const uint32_t aoffA = (uint32_t)((wm + (lane & 15)) * ROWB + (lane >> 4) * 16);
    const uint32_t aoffB = (uint32_t)((wn + (lane & 7)) * ROWB + ((lane >> 3) & 1) * 16);

    const int nch = K >> 5;
    for (int c = 0; c < nch; c++){
        const int p = c & 1;
        if (c + 1 < nch){
            const uint32_t st = sbase + (p ^ 1) * STAGE_B;
            const int k0 = (c + 1) << 5;
            ldB_async(st + T_AHI, Ah, browG, K, k0, tid);
            ldB_async(st + T_ALO, Al, browG, K, k0, tid);
            ldB_async(st + T_BHI, Bh, bcolG, K, k0, tid);
            ldB_async(st + T_BLO, Bl, bcolG, K, k0, tid);
            CP_COMMIT();
        }
        const uint32_t sb = sbase + p * STAGE_B;
        #pragma unroll
        for (int ks = 0; ks < 2; ks++){
            const uint32_t kb = ks * 32;
            // Preload all B fragments for this k-step (16 regs live)
            uint32_t bh[4][2], bl[4][2];
            #pragma unroll
            for (int nt = 0; nt < 4; nt++){
                ldsm2(bh[nt], sb + T_BHI + aoffB + nt * (8 * ROWB) + kb);
                ldsm2(bl[nt], sb + T_BLO + aoffB + nt * (8 * ROWB) + kb);
            }
            // Stream A fragments per mt (8 regs live at a time)
            #pragma unroll
            for (int mt = 0; mt < 4; mt++){
                uint32_t ah4[4], al4[4];
                ldsm4(ah4, sb + T_AHI + aoffA + mt * (16 * ROWB) + kb);
                ldsm4(al4, sb + T_ALO + aoffA + mt * (16 * ROWB) + kb);
                #pragma unroll
                for (int nt = 0; nt < 4; nt++){
                    mma_bf16(acc[mt][nt], ah4, bh[nt]);
                    mma_bf16(acc[mt][nt], ah4, bl[nt]);
                    mma_bf16(acc[mt][nt], al4, bh[nt]);
                }
            }
        }
        CP_WAIT0();
        __syncthreads();
    }

    const int g = lane >> 2, t = lane & 3;
    #pragma unroll
    for (int mt = 0; mt < 4; mt++){
        #pragma unroll
        for (int nt = 0; nt < 4; nt++){
            const long long r  = browG + wm + mt * 16 + g;
            const int       cc = bcolG + wn + nt * 8 + t * 2;
            const float* a = acc[mt][nt];
            const float b0 = bias ? bias[cc]     : 0.f;
            const float b1 = bias ? bias[cc + 1] : 0.f;
            const float v0 = a[0] + b0, v1 = a[1] + b1;
            const float v2 = a[2] + b0, v3 = a[3] + b1;
            if (mode == 0){
                float* Cz = Cf + (long long)z * sC;
                *(float2*)(Cz + r * (long long)Nc + cc)       = make_float2(v0, v1);
                *(float2*)(Cz + (r + 8) * (long long)Nc + cc) = make_float2(v2, v3);
            } else {
                __nv_bfloat16 h0 = __float2bfloat16(v0), h1 = __float2bfloat16(v1);
                __nv_bfloat16 h2 = __float2bfloat16(v2), h3 = __float2bfloat16(v3);
                __nv_bfloat162 hh0; hh0.x = h0; hh0.y = h1;
                __nv_bfloat162 hh1; hh1.x = h2; hh1.y = h3;
                __nv_bfloat162 ll0;
                ll0.x = __float2bfloat16(v0 - __bfloat162float(h0));
                ll0.y = __float2bfloat16(v1 - __bfloat162float(h1));
                __nv_bfloat162 ll1;
                ll1.x = __float2bfloat16(v2 - __bfloat162float(h2));
                ll1.y = __float2bfloat16(v3 - __bfloat162float(h3));
                *(__nv_bfloat162*)(Chi + r * (long long)Nc + cc)       = hh0;
                *(__nv_bfloat162*)(Chi + (r + 8) * (long long)Nc + cc) = hh1;
                *(__nv_bfloat162*)(Clo + r * (long long)Nc + cc)       = ll0;
                *(__nv_bfloat162*)(Clo + (r + 8) * (long long)Nc + cc) = ll1;
            }
        }
    }
}

// ---------------- fp16 single-term PV GEMM NT --------------------------------
// O[q,d] = P[q,k] @ Vt[d,k]^T. 1 MMA per K16 step. 2 tiles/stage, 2 CTAs/SM.
__global__ __launch_bounds__(256, 2) void gemm_pv_f16(
    const __half* __restrict__ Pg, const __half* __restrict__ Vg,
    float* __restrict__ O)
{
    extern __shared__ char smem[];
    const int tid = threadIdx.x, wid = tid >> 5, lane = tid & 31;
    const int browG = blockIdx.y * 128, bcolG = blockIdx.x * 128;
    const int z = blockIdx.z;

    const __half* A = Pg + (size_t)z * SEQ * SEQ;
    const __half* B = Vg + (size_t)z * DIM * SEQ;
    float* Ob = O + (size_t)z * SEQ * DIM;

    float acc[4][4][4];
    #pragma unroll
    for (int i = 0; i < 4; i++)
        #pragma unroll
        for (int j = 0; j < 4; j++)
            #pragma unroll
            for (int k = 0; k < 4; k++) acc[i][j][k] = 0.f;

    const uint32_t sbase = smem_u32(smem);

    ldB_async(sbase + 0,      A, browG, SEQ, 0, tid);
    ldB_async(sbase + TILE_B, B, bcolG, SEQ, 0, tid);
    CP_COMMIT();
    CP_WAIT0();
    __syncthreads();

    const int wm = (wid & 1) * 64;
    const int wn = (wid >> 1) * 32;
    const uint32_t aoffA = (uint32_t)((wm + (lane & 15)) * ROWB + (lane >> 4) * 16);
    const uint32_t aoffB = (uint32_t)((wn + (lane & 7)) * ROWB + ((lane >> 3) & 1) * 16);

    const int nch = SEQ >> 5;   // 128
    for (int c = 0; c < nch; c++){
        const int p = c & 1;
        if (c + 1 < nch){
            const uint32_t st = sbase + (p ^ 1) * STAGE_PV;
            const int k0 = (c + 1) << 5;
            ldB_async(st + 0,      A, browG, SEQ, k0, tid);
            ldB_async(st + TILE_B, B, bcolG, SEQ, k0, tid);
            CP_COMMIT();
        }
        const uint32_t sb = sbase + p * STAGE_PV;
        #pragma unroll
        for (int ks = 0; ks < 2; ks++){
            const uint32_t kb = ks * 32;
            uint32_t bh[4][2];
            #pragma unroll
            for (int nt = 0; nt < 4; nt++)
                ldsm2(bh[nt], sb + TILE_B + aoffB + nt * (8 * ROWB) + kb);
            #pragma unroll
            for (int mt = 0; mt < 4; mt++){
                uint32_t ah4[4];
                ldsm4(ah4, sb + 0 + aoffA + mt * (16 * ROWB) + kb);
                #pragma unroll
                for (int nt = 0; nt < 4; nt++)
                    mma_f16(acc[mt][nt], ah4, bh[nt]);
            }
        }
        CP_WAIT0();
        __syncthreads();
    }

    const int g = lane >> 2, t = lane & 3;
    #pragma unroll
    for (int mt = 0; mt < 4; mt++)
        #pragma unroll
        for (int nt = 0; nt < 4; nt++){
            const long long r  = browG + wm + mt * 16 + g;
            const int       cc = bcolG + wn + nt * 8 + t * 2;
            const float* a = acc[mt][nt];
            *(float2*)(Ob + r * (long long)DIM + cc)       = make_float2(a[0], a[1]);
            *(float2*)(Ob + (r + 8) * (long long)DIM + cc) = make_float2(a[2], a[3]);
        }
}

// ---------------- small kernels ----------------------------------------------
__global__ void split_pair(const float* __restrict__ x, __nv_bfloat16* __restrict__ hi,
                           __nv_bfloat16* __restrict__ lo, long long n)
{
    long long i = (long long)blockIdx.x * blockDim.x + threadIdx.x;
    const long long stride = (long long)gridDim.x * blockDim.x;
    for (; i < n; i += stride){
        const float v = x[i];
        __nv_bfloat16 h = __float2bfloat16(v);
        hi[i] = h;
        lo[i] = __float2bfloat16(v - __bfloat162float(h));
    }
}

__global__ void transpose_h(const float* __restrict__ V, __half* __restrict__ Th)
{
    __shared__ float t[32][33];
    const int b = blockIdx.z;
    const int d0 = blockIdx.x * 32, k0 = blockIdx.y * 32;
    const float* Vb = V + (size_t)b * SEQ * DIM;
    #pragma unroll
    for (int r = 0; r < 4; r++)
        t[threadIdx.y + 8 * r][threadIdx.x] =
            Vb[(size_t)(k0 + threadIdx.y + 8 * r) * DIM + d0 + threadIdx.x];
    __syncthreads();
    __half* Thb = Th + (size_t)b * DIM * SEQ;
    #pragma unroll
    for (int r = 0; r < 4; r++){
        const float v = t[threadIdx.x][threadIdx.y + 8 * r];
        Thb[(size_t)(d0 + threadIdx.y + 8 * r) * SEQ + k0 + threadIdx.x] = __float2half(v);
    }
}

__global__ void col_lse(const float* __restrict__ S, float* __restrict__ L)
{
    const int b = blockIdx.y;
    const int k = blockIdx.x * 32 + threadIdx.x;
    const float* Sb = S + (size_t)b * SEQ * SEQ;

    float m = -INFINITY, s = 0.f;
    for (int q = threadIdx.y; q < SEQ; q += 8) {
        const float v = Sb[(size_t)q * SEQ + k];
        const float mn = fmaxf(m, v);
        s = s * __expf(m - mn) + __expf(v - mn);
        m = mn;
    }
    __shared__ float sm[8][33], ss[8][33];
    sm[threadIdx.y][threadIdx.x] = m;
    ss[threadIdx.y][threadIdx.x] = s;
    __syncthreads();
    if (threadIdx.y == 0) {
        float M = m, Sa = s;
        #pragma unroll
        for (int t = 1; t < 8; t++) {
            const float m2 = sm[t][threadIdx.x], s2 = ss[t][threadIdx.x];
            const float Mn = fmaxf(M, m2);
            Sa = Sa * __expf(M - Mn) + s2 * __expf(m2 - Mn);
            M = Mn;
        }
        L[b * SEQ + k] = M + __logf(Sa);
    }
}

// P = exp(S - L[k]) -> fp16, one pass.
__global__ void compute_p(const float* __restrict__ S, const float* __restrict__ L,
                          __half* __restrict__ Ph)
{
    const long long n4 = (long long)BATCH * SEQ * SEQ / 4;
    long long i = (long long)blockIdx.x * blockDim.x + threadIdx.x;
    const long long stride = (long long)gridDim.x * blockDim.x;
    for (; i < n4; i += stride){
        const long long e = i * 4;
        const int b = (int)(e / ((long long)SEQ * SEQ));
        const int k = (int)(e % SEQ);
        const float4 sv = *(const float4*)(S + e);
        const float4 lv = *(const float4*)(L + b * SEQ + k);
        __half2 hA, hB;
        hA.x = __float2half(__expf(sv.x - lv.x));
        hA.y = __float2half(__expf(sv.y - lv.y));
        hB.x = __float2half(__expf(sv.z - lv.z));
        hB.y = __float2half(__expf(sv.w - lv.w));
        *(__half2*)(Ph + e)     = hA;
        *(__half2*)(Ph + e + 2) = hB;
    }
}

// ---------------- launcher ---------------------------------------------------
extern "C" void kernel_launch(void* const* d_in, const int* in_sizes, int n_in,
                              void* d_out, int out_size)
{
    const float* x  = (const float*)d_in[0];
    const float* Wq = (const float*)d_in[1];
    const float* bq = (const float*)d_in[2];
    const float* Wk = (const float*)d_in[3];
    const float* bk = (const float*)d_in[4];
    const float* Wv = (const float*)d_in[5];
    const float* bv = (const float*)d_in[6];
    float* out = (float*)d_out;

    __nv_bfloat16 *xh, *xl, *Wh, *Wl, *Qh, *Ql, *Kh, *Kl;
    __half *Vth, *Ph;
    float *Vf, *pS, *pL;
    cudaGetSymbolAddress((void**)&xh,  g_xh);  cudaGetSymbolAddress((void**)&xl,  g_xl);
    cudaGetSymbolAddress((void**)&Wh,  g_Wh);  cudaGetSymbolAddress((void**)&Wl,  g_Wl);
    cudaGetSymbolAddress((void**)&Qh,  g_Qh);  cudaGetSymbolAddress((void**)&Ql,  g_Ql);
    cudaGetSymbolAddress((void**)&Kh,  g_Kh);  cudaGetSymbolAddress((void**)&Kl,  g_Kl);
    cudaGetSymbolAddress((void**)&Vth, g_Vth); cudaGetSymbolAddress((void**)&Ph,  g_Ph);
    cudaGetSymbolAddress((void**)&Vf,  g_V);
    cudaGetSymbolAddress((void**)&pS,  g_S);   cudaGetSymbolAddress((void**)&pL,  g_L);

    cudaFuncSetAttribute(gemm_bf16_nt, cudaFuncAttributeMaxDynamicSharedMemorySize, SM_TOTAL);
    cudaFuncSetAttribute(gemm_pv_f16,  cudaFuncAttributeMaxDynamicSharedMemorySize, SM_PV);

    // 1) hi/lo splits
    split_pair<<<1024, 256>>>(x,  xh, xl, (long long)MQKV * DIM);
    split_pair<<<256, 256>>>(Wq, Wh + 0 * DIM * DIM, Wl + 0 * DIM * DIM, (long long)DIM * DIM);
    split_pair<<<256, 256>>>(Wk, Wh + 1 * DIM * DIM, Wl + 1 * DIM * DIM, (long long)DIM * DIM);
    split_pair<<<256, 256>>>(Wv, Wh + 2 * DIM * DIM, Wl + 2 * DIM * DIM, (long long)DIM * DIM);

    // 2) projections
    {
        dim3 g(DIM / 128, MQKV / 128, 1);
        gemm_bf16_nt<<<g, 256, SM_TOTAL>>>(xh, xl, Wh + 0 * DIM * DIM, Wl + 0 * DIM * DIM, bq,
                                           nullptr, Qh, Ql, DIM, DIM, 1, 0, 0, 0);
        gemm_bf16_nt<<<g, 256, SM_TOTAL>>>(xh, xl, Wh + 1 * DIM * DIM, Wl + 1 * DIM * DIM, bk,
                                           nullptr, Kh, Kl, DIM, DIM, 1, 0, 0, 0);
        gemm_bf16_nt<<<g, 256, SM_TOTAL>>>(xh, xl, Wh + 2 * DIM * DIM, Wl + 2 * DIM * DIM, bv,
                                           Vf, nullptr, nullptr, DIM, DIM, 0, 0, 0, 0);
    }

    // 3) V -> Vt (fp16)
    transpose_h<<<dim3(DIM / 32, SEQ / 32, BATCH), dim3(32, 8)>>>(Vf, Vth);

    // 4) S = Q @ K^T (batched, bf16 3-split: accuracy-critical)
    gemm_bf16_nt<<<dim3(SEQ / 128, SEQ / 128, BATCH), 256, SM_TOTAL>>>(
        Qh, Ql, Kh, Kl, nullptr, pS, nullptr, nullptr,
        DIM, SEQ, 0, (long long)SEQ * DIM, (long long)SEQ * DIM, (long long)SEQ * SEQ);

    // 5) logsumexp over query axis
    col_lse<<<dim3(SEQ / 32, BATCH), dim3(32, 8)>>>(pS, pL);

    // 6) P = exp(S - L), fp16, single pass
    compute_p<<<2048, 256>>>(pS, pL, Ph);

    // 7) O = P @ Vt^T  (fp16 single-term GEMM)
    gemm_pv_f16<<<dim3(DIM / 128, SEQ / 128, BATCH), 256, SM_PV>>>(Ph, Vth, out);
}